// round 8
// baseline (speedup 1.0000x reference)
#include <cuda_runtime.h>
#include <cstdint>

// ============================================================================
// Problem constants — s4 (nibble-packed) pipeline
// ============================================================================
#define D_DIM 4096
#define ROWB 2048               // packed bytes per row (4096 int4 / 2)
#define BM 128
#define BN 128
#define BK 64                   // BYTES of K per pipeline stage (= 128 k-values)
#define NSTAGE 4
#define KT_ITERS (ROWB / BK)    // 32
#define THREADS 256

#define A_STAGE 8192            // 128 rows x 64B
#define B_STAGE 8192
#define STAGE_BYTES (A_STAGE + B_STAGE)

// ============================================================================
// Scratch (device globals; no allocation allowed)
// ============================================================================
__device__ __align__(1024) unsigned char g_qx[(size_t)D_DIM * ROWB]; // s4-packed activations
__device__ __align__(1024) unsigned char g_wq[(size_t)D_DIM * ROWB]; // s4-packed weights
__device__ float g_sx[D_DIM];                                         // activation row scales

// ============================================================================
// PTX helpers — base ISA only
// ============================================================================
__device__ __forceinline__ uint32_t smem_u32(const void* p) {
    uint32_t a;
    asm("{ .reg .u64 t; cvta.to.shared.u64 t, %1; cvt.u32.u64 %0, t; }" : "=r"(a) : "l"(p));
    return a;
}

#define CP_ASYNC16(dst, src) \
    asm volatile("cp.async.cg.shared.global [%0], [%1], 16;" :: "r"(dst), "l"(src))
#define CP_COMMIT() asm volatile("cp.async.commit_group;" ::: "memory")
#define CP_WAIT2()  asm volatile("cp.async.wait_group 2;" ::: "memory")

#define LDM_X4(r, addr) \
    asm volatile("ldmatrix.sync.aligned.m8n8.x4.shared.b16 {%0,%1,%2,%3}, [%4];" \
                 : "=r"((r)[0]), "=r"((r)[1]), "=r"((r)[2]), "=r"((r)[3]) : "r"(addr))

// s4 x s4 -> s32, k64: 2x the MACs of s8 k32 at the same fragment geometry.
#define MMA_S4(c, a, b0, b1) \
    asm volatile("mma.sync.aligned.m16n8k64.row.col.s32.s4.s4.s32 " \
                 "{%0,%1,%2,%3},{%4,%5,%6,%7},{%8,%9},{%0,%1,%2,%3};" \
                 : "+r"((c)[0]), "+r"((c)[1]), "+r"((c)[2]), "+r"((c)[3]) \
                 : "r"((a)[0]), "r"((a)[1]), "r"((a)[2]), "r"((a)[3]), "r"(b0), "r"(b1))

// SMEM tile: rows x 64B, 16B chunks swizzled: phys_chunk = chunk ^ ((row>>1)&3)
__device__ __forceinline__ uint32_t tile_off(int row, int chunk) {
    return (uint32_t)(row * 64 + ((chunk ^ ((row >> 1) & 3)) << 4));
}

// ============================================================================
// Kernel 1 (fused prep):
//   blocks [0,4096):    Hadamard-256 + per-row int4 quantize -> nibble pack
//   blocks [4096,8192): weight int32 -> nibble pack (one weight row per block)
// Pack order: nibble i of a u32 = element (4*i) ... i.e. low nibble = lowest k.
// ============================================================================
__global__ __launch_bounds__(512) void prep_kernel(
    const float* __restrict__ x, const int4* __restrict__ wi,
    uint32_t* __restrict__ qx, uint32_t* __restrict__ wq, float* __restrict__ sxv)
{
    if (blockIdx.x >= 4096) {
        // one weight row per block: 4096 ints -> 512 packed u32
        int row = blockIdx.x - 4096;
        int t = threadIdx.x;
        const int4* wr = wi + (size_t)row * 1024 + t * 2;
        int4 v0 = wr[0], v1 = wr[1];
        uint32_t p =  ((uint32_t)v0.x & 0xF)        | (((uint32_t)v0.y & 0xF) << 4)
                   | (((uint32_t)v0.z & 0xF) << 8)  | (((uint32_t)v0.w & 0xF) << 12)
                   | (((uint32_t)v1.x & 0xF) << 16) | (((uint32_t)v1.y & 0xF) << 20)
                   | (((uint32_t)v1.z & 0xF) << 24) | (((uint32_t)v1.w & 0xF) << 28);
        wq[(size_t)row * 512 + t] = p;
        return;
    }

    // ---- Hadamard + quantize: one x-row per block, warp w = 256-elem segment
    // element index within segment: i = lane*8 + j  (j = low 3 bits)
    __shared__ float smax[16];
    int row  = blockIdx.x;
    int w    = threadIdx.x >> 5;
    int lane = threadIdx.x & 31;

    const float* xr = x + (size_t)row * D_DIM + w * 256 + lane * 8;
    float v[8];
    {
        float4 u0 = *(const float4*)xr;
        float4 u1 = *(const float4*)(xr + 4);
        v[0] = u0.x; v[1] = u0.y; v[2] = u0.z; v[3] = u0.w;
        v[4] = u1.x; v[5] = u1.y; v[6] = u1.z; v[7] = u1.w;
    }

    // strides 1,2,4: j-bit butterflies (in-register)
#pragma unroll
    for (int b = 1; b < 8; b <<= 1) {
#pragma unroll
        for (int j = 0; j < 8; j++) {
            if (!(j & b)) {
                float a = v[j], c = v[j | b];
                v[j] = a + c; v[j | b] = a - c;
            }
        }
    }
    // strides 8..128: lane-bit butterflies (shfl_xor s = 1..16)
#pragma unroll
    for (int s = 1; s < 32; s <<= 1) {
#pragma unroll
        for (int j = 0; j < 8; j++) {
            float o = __shfl_xor_sync(0xFFFFFFFFu, v[j], s);
            v[j] = (lane & s) ? (o - v[j]) : (v[j] + o);
        }
    }
#pragma unroll
    for (int j = 0; j < 8; j++) v[j] *= 0.0625f;   // 1/sqrt(256)

    float mx = 0.0f;
#pragma unroll
    for (int j = 0; j < 8; j++) mx = fmaxf(mx, fabsf(v[j]));
#pragma unroll
    for (int s = 16; s; s >>= 1) mx = fmaxf(mx, __shfl_xor_sync(0xFFFFFFFFu, mx, s));
    if (lane == 0) smax[w] = mx;
    __syncthreads();
    float tot = smax[0];
#pragma unroll
    for (int i = 1; i < 16; i++) tot = fmaxf(tot, smax[i]);

    if (threadIdx.x == 0) sxv[row] = tot * (1.0f / 7.0f);
    float inv = 7.0f / tot;

    uint32_t p = 0;
#pragma unroll
    for (int j = 0; j < 8; j++) {
        float q = rintf(v[j] * inv);               // round-half-even == jnp.round
        q = fminf(fmaxf(q, -8.0f), 7.0f);
        p |= ((uint32_t)(int)q & 0xF) << (4 * j);
    }
    qx[(size_t)row * 512 + w * 32 + lane] = p;
}

// ============================================================================
// Kernel 2: s4 GEMM, tile 128x128, 256 threads (8 warps, 2Mx4N, warp 64x32),
// 4-stage cp.async pipeline, 2 CTAs/SM, fused dequant epilogue.
// Fragment note: the s4-k64 mma fragment is the byte-level reinterpretation of
// the s8-k32 fragment, so ldmatrix addressing is unchanged from the passing
// int8 kernel; each 32B of a row now covers 64 k-values.
// ============================================================================
__global__ __launch_bounds__(THREADS, 2) void gemm_kernel(
    const unsigned char* __restrict__ gA,   // [4096, 2048B] s4-packed (m,k)
    const unsigned char* __restrict__ gB,   // [4096, 2048B] s4-packed (n,k)
    const float* __restrict__ sx,
    const float* __restrict__ ws,
    const float* __restrict__ bias,
    float* __restrict__ out)
{
    extern __shared__ char smem[];
    uint32_t sbase = smem_u32(smem);
    const uint32_t sA0 = sbase;
    const uint32_t sB0 = sbase + NSTAGE * A_STAGE;

    int tid  = threadIdx.x;
    int lane = tid & 31;
    int wid  = tid >> 5;
    int m0 = blockIdx.x * BM;
    int n0 = blockIdx.y * BN;
    int wm = wid & 1;           // 2 warps over M
    int wn = wid >> 1;          // 4 warps over N
    int Amb = wm * 64;
    int Bnb = wn * 32;
    int i8 = lane & 7, g = lane >> 3;

    int acc[4][4][4];
#pragma unroll
    for (int a = 0; a < 4; a++)
#pragma unroll
        for (int b = 0; b < 4; b++)
#pragma unroll
            for (int c = 0; c < 4; c++) acc[a][b][c] = 0;

    // per-stage loads: 512 chunks A (2/thread) + 512 chunks B (2/thread)
    int row0 = tid >> 2, ch0 = tid & 3;
    int row1 = (tid + 256) >> 2;
    const unsigned char* gA0 = gA + (size_t)(m0 + row0) * ROWB + ch0 * 16;
    const unsigned char* gA1 = gA + (size_t)(m0 + row1) * ROWB + ch0 * 16;
    const unsigned char* gB0 = gB + (size_t)(n0 + row0) * ROWB + ch0 * 16;
    const unsigned char* gB1 = gB + (size_t)(n0 + row1) * ROWB + ch0 * 16;
    uint32_t off0 = tile_off(row0, ch0);
    uint32_t off1 = tile_off(row1, ch0);

    auto load_stage = [&](int kt, int buf) {
        int kb = kt * BK;
        uint32_t dA = sA0 + buf * A_STAGE;
        uint32_t dB = sB0 + buf * B_STAGE;
        CP_ASYNC16(dA + off0, gA0 + kb);
        CP_ASYNC16(dA + off1, gA1 + kb);
        CP_ASYNC16(dB + off0, gB0 + kb);
        CP_ASYNC16(dB + off1, gB1 + kb);
    };

    // precomputed ldmatrix offsets (each x4 = 16 rows x 32B = one k64 fragment)
    uint32_t aoffs[4][2], boffs[2][2];
#pragma unroll
    for (int mb = 0; mb < 4; mb++) {
        int row = Amb + mb * 16 + i8 + (g & 1) * 8;
#pragma unroll
        for (int ks = 0; ks < 2; ks++)
            aoffs[mb][ks] = tile_off(row, ks * 2 + (g >> 1));
    }
#pragma unroll
    for (int np = 0; np < 2; np++) {
        int row = Bnb + np * 16 + i8 + (g >> 1) * 8;
#pragma unroll
        for (int ks = 0; ks < 2; ks++)
            boffs[np][ks] = tile_off(row, ks * 2 + (g & 1));
    }

#pragma unroll
    for (int s = 0; s < NSTAGE - 1; s++) {
        load_stage(s, s);
        CP_COMMIT();
    }

    for (int kt = 0; kt < KT_ITERS; kt++) {
        CP_WAIT2();
        __syncthreads();

        int ldkt = kt + NSTAGE - 1;
        if (ldkt < KT_ITERS) load_stage(ldkt, ldkt & (NSTAGE - 1));
        CP_COMMIT();

        uint32_t sA = sA0 + (kt & (NSTAGE - 1)) * A_STAGE;
        uint32_t sB = sB0 + (kt & (NSTAGE - 1)) * B_STAGE;

#pragma unroll
        for (int ks = 0; ks < 2; ks++) {          // two k64 steps per stage
            uint32_t a[4][4], b[2][4];
#pragma unroll
            for (int mb = 0; mb < 4; mb++) LDM_X4(a[mb], sA + aoffs[mb][ks]);
#pragma unroll
            for (int np = 0; np < 2; np++) LDM_X4(b[np], sB + boffs[np][ks]);
#pragma unroll
            for (int mb = 0; mb < 4; mb++)
#pragma unroll
                for (int nb = 0; nb < 4; nb++)
                    MMA_S4(acc[mb][nb], a[mb],
                           b[nb >> 1][(nb & 1) * 2], b[nb >> 1][(nb & 1) * 2 + 1]);
        }
    }

    // ---- epilogue: dequant + bias, float2 stores ----
#pragma unroll
    for (int mb = 0; mb < 4; mb++) {
        int r0 = m0 + Amb + mb * 16 + (lane >> 2);
        float sx0 = sx[r0], sx1 = sx[r0 + 8];
#pragma unroll
        for (int nb = 0; nb < 4; nb++) {
            int c0 = n0 + Bnb + nb * 8 + (lane & 3) * 2;
            float w0 = ws[c0],  w1 = ws[c0 + 1];
            float f0 = bias[c0], f1 = bias[c0 + 1];
            float2 v0, v1;
            v0.x = (float)acc[mb][nb][0] * sx0 * w0 + f0;
            v0.y = (float)acc[mb][nb][1] * sx0 * w1 + f1;
            v1.x = (float)acc[mb][nb][2] * sx1 * w0 + f0;
            v1.y = (float)acc[mb][nb][3] * sx1 * w1 + f1;
            *(float2*)&out[(size_t)r0 * D_DIM + c0]       = v0;
            *(float2*)&out[(size_t)(r0 + 8) * D_DIM + c0] = v1;
        }
    }
}

// ============================================================================
// Host launcher
// ============================================================================
extern "C" void kernel_launch(void* const* d_in, const int* in_sizes, int n_in,
                              void* d_out, int out_size)
{
    const float* x    = (const float*)d_in[0];
    const int*   wi   = (const int*)  d_in[1];
    const float* wsc  = (const float*)d_in[2];
    const float* bias = (const float*)d_in[3];
    float*       out  = (float*)d_out;

    void *pqx = nullptr, *pwq = nullptr, *psx = nullptr;
    cudaGetSymbolAddress(&pqx, g_qx);
    cudaGetSymbolAddress(&pwq, g_wq);
    cudaGetSymbolAddress(&psx, g_sx);

    static bool attr_set = false;
    if (!attr_set) {
        cudaFuncSetAttribute(gemm_kernel, cudaFuncAttributeMaxDynamicSharedMemorySize,
                             NSTAGE * STAGE_BYTES);
        attr_set = true;
    }

    // 1) fused prep: Hadamard+quantize+pack (blocks 0..4095) + weight pack (4096..8191)
    prep_kernel<<<8192, 512>>>(x, (const int4*)wi,
                               (uint32_t*)pqx, (uint32_t*)pwq, (float*)psx);

    // 2) s4 GEMM + fused dequant
    dim3 grid(D_DIM / BM, D_DIM / BN, 1);
    gemm_kernel<<<grid, THREADS, NSTAGE * STAGE_BYTES>>>(
        (const unsigned char*)pqx, (const unsigned char*)pwq,
        (const float*)psx, wsc, bias, out);
}

// round 9
// speedup vs baseline: 2.6693x; 2.6693x over previous
#include <cuda_runtime.h>
#include <cuda_fp8.h>
#include <cstdint>

// ============================================================================
// Problem constants
// ============================================================================
#define D_DIM 4096
#define BM 128
#define BN 128
#define BK 64                   // bytes of K per pipeline stage
#define NSTAGE 4
#define KT_ITERS (D_DIM / BK)   // 64
#define THREADS 256

#define A_STAGE 8192            // 128 rows x 64B
#define B_STAGE 8192
#define STAGE_BYTES (A_STAGE + B_STAGE)

#define NSPLIT 3072             // cols [0,NSPLIT) -> s8 kernel, rest -> e4m3 kernel

// ============================================================================
// Scratch (device globals; no allocation allowed)
// ============================================================================
__device__ __align__(1024) signed char   g_qx [(size_t)D_DIM * D_DIM]; // int8 activations
__device__ __align__(1024) signed char   g_wq [(size_t)D_DIM * D_DIM]; // int8 weights
__device__ __align__(1024) unsigned char g_qx8[(size_t)D_DIM * D_DIM]; // e4m3 activations
__device__ __align__(1024) unsigned char g_wq8[(size_t)D_DIM * D_DIM]; // e4m3 weights
__device__ float g_sx[D_DIM];                                           // activation row scales

// ============================================================================
// PTX helpers — base ISA only
// ============================================================================
__device__ __forceinline__ uint32_t smem_u32(const void* p) {
    uint32_t a;
    asm("{ .reg .u64 t; cvta.to.shared.u64 t, %1; cvt.u32.u64 %0, t; }" : "=r"(a) : "l"(p));
    return a;
}

#define CP_ASYNC16(dst, src) \
    asm volatile("cp.async.cg.shared.global [%0], [%1], 16;" :: "r"(dst), "l"(src))
#define CP_COMMIT() asm volatile("cp.async.commit_group;" ::: "memory")
#define CP_WAIT2()  asm volatile("cp.async.wait_group 2;" ::: "memory")

#define LDM_X4(r, addr) \
    asm volatile("ldmatrix.sync.aligned.m8n8.x4.shared.b16 {%0,%1,%2,%3}, [%4];" \
                 : "=r"((r)[0]), "=r"((r)[1]), "=r"((r)[2]), "=r"((r)[3]) : "r"(addr))

#define MMA_S8(c, a, b0, b1) \
    asm volatile("mma.sync.aligned.m16n8k32.row.col.s32.s8.s8.s32 " \
                 "{%0,%1,%2,%3},{%4,%5,%6,%7},{%8,%9},{%0,%1,%2,%3};" \
                 : "+r"((c)[0]), "+r"((c)[1]), "+r"((c)[2]), "+r"((c)[3]) \
                 : "r"((a)[0]), "r"((a)[1]), "r"((a)[2]), "r"((a)[3]), "r"(b0), "r"(b1))

#define MMA_E4M3(c, a, b0, b1) \
    asm volatile("mma.sync.aligned.m16n8k32.row.col.f32.e4m3.e4m3.f32 " \
                 "{%0,%1,%2,%3},{%4,%5,%6,%7},{%8,%9},{%0,%1,%2,%3};" \
                 : "+f"((c)[0]), "+f"((c)[1]), "+f"((c)[2]), "+f"((c)[3]) \
                 : "r"((a)[0]), "r"((a)[1]), "r"((a)[2]), "r"((a)[3]), "r"(b0), "r"(b1))

// SMEM tile: rows x 64B, 16B chunks swizzled: phys_chunk = chunk ^ ((row>>1)&3)
__device__ __forceinline__ uint32_t tile_off(int row, int chunk) {
    return (uint32_t)(row * 64 + ((chunk ^ ((row >> 1) & 3)) << 4));
}

__device__ __forceinline__ unsigned char to_e4m3(float f) {
    return __nv_fp8_e4m3(f).__x;
}

// ============================================================================
// Kernel 1 (fused prep):
//   blocks [0,4096):    Hadamard-256 + per-row int4 quantize -> s8 AND e4m3
//   blocks [4096,8192): weight int32 -> s8 AND e4m3 (one weight row per block)
// Activation layout: elem i = lane*8 + j  (strides 1,2,4 in-register; 8..128 shfl)
// ============================================================================
__global__ __launch_bounds__(512) void prep_kernel(
    const float* __restrict__ x, const int4* __restrict__ wi,
    signed char* __restrict__ qx, signed char* __restrict__ wq,
    unsigned char* __restrict__ qx8, unsigned char* __restrict__ wq8,
    float* __restrict__ sxv)
{
    if (blockIdx.x >= 4096) {
        // one weight row per block: 4096 ints, 8 per thread (contiguous)
        int row = blockIdx.x - 4096;
        int t = threadIdx.x;
        const int4* wr = wi + (size_t)row * 1024 + t * 2;
        int4 v0 = wr[0], v1 = wr[1];
        uint32_t p0 = ((uint32_t)v0.x & 0xFF)        | (((uint32_t)v0.y & 0xFF) << 8)
                    | (((uint32_t)v0.z & 0xFF) << 16) | (((uint32_t)v0.w & 0xFF) << 24);
        uint32_t p1 = ((uint32_t)v1.x & 0xFF)        | (((uint32_t)v1.y & 0xFF) << 8)
                    | (((uint32_t)v1.z & 0xFF) << 16) | (((uint32_t)v1.w & 0xFF) << 24);
        uint2 ps = make_uint2(p0, p1);
        *(uint2*)&wq[(size_t)row * D_DIM + t * 8] = ps;

        uint32_t f0 =  (uint32_t)to_e4m3((float)v0.x)
                    | ((uint32_t)to_e4m3((float)v0.y) << 8)
                    | ((uint32_t)to_e4m3((float)v0.z) << 16)
                    | ((uint32_t)to_e4m3((float)v0.w) << 24);
        uint32_t f1 =  (uint32_t)to_e4m3((float)v1.x)
                    | ((uint32_t)to_e4m3((float)v1.y) << 8)
                    | ((uint32_t)to_e4m3((float)v1.z) << 16)
                    | ((uint32_t)to_e4m3((float)v1.w) << 24);
        *(uint2*)&wq8[(size_t)row * D_DIM + t * 8] = make_uint2(f0, f1);
        return;
    }

    // ---- Hadamard + quantize: one x-row per block, warp w = 256-elem segment
    __shared__ float smax[16];
    int row  = blockIdx.x;
    int w    = threadIdx.x >> 5;
    int lane = threadIdx.x & 31;

    const float* xr = x + (size_t)row * D_DIM + w * 256 + lane * 8;
    float v[8];
    {
        float4 u0 = *(const float4*)xr;
        float4 u1 = *(const float4*)(xr + 4);
        v[0] = u0.x; v[1] = u0.y; v[2] = u0.z; v[3] = u0.w;
        v[4] = u1.x; v[5] = u1.y; v[6] = u1.z; v[7] = u1.w;
    }

    // strides 1,2,4 (j bits), in-register
#pragma unroll
    for (int b = 1; b < 8; b <<= 1) {
#pragma unroll
        for (int j = 0; j < 8; j++) {
            if (!(j & b)) {
                float a = v[j], c = v[j | b];
                v[j] = a + c; v[j | b] = a - c;
            }
        }
    }
    // strides 8..128 (lane bits), shfl
#pragma unroll
    for (int s = 1; s < 32; s <<= 1) {
#pragma unroll
        for (int j = 0; j < 8; j++) {
            float o = __shfl_xor_sync(0xFFFFFFFFu, v[j], s);
            v[j] = (lane & s) ? (o - v[j]) : (v[j] + o);
        }
    }
#pragma unroll
    for (int j = 0; j < 8; j++) v[j] *= 0.0625f;   // 1/sqrt(256)

    float mx = 0.0f;
#pragma unroll
    for (int j = 0; j < 8; j++) mx = fmaxf(mx, fabsf(v[j]));
#pragma unroll
    for (int s = 16; s; s >>= 1) mx = fmaxf(mx, __shfl_xor_sync(0xFFFFFFFFu, mx, s));
    if (lane == 0) smax[w] = mx;
    __syncthreads();
    float tot = smax[0];
#pragma unroll
    for (int i = 1; i < 16; i++) tot = fmaxf(tot, smax[i]);

    if (threadIdx.x == 0) sxv[row] = tot * (1.0f / 7.0f);
    float inv = 7.0f / tot;

    int   qi[8];
#pragma unroll
    for (int j = 0; j < 8; j++) {
        float q = rintf(v[j] * inv);               // round-half-even == jnp.round
        q = fminf(fmaxf(q, -8.0f), 7.0f);
        qi[j] = (int)q;
    }
    uint32_t p0 = ((uint32_t)qi[0] & 0xFF)        | (((uint32_t)qi[1] & 0xFF) << 8)
                | (((uint32_t)qi[2] & 0xFF) << 16) | (((uint32_t)qi[3] & 0xFF) << 24);
    uint32_t p1 = ((uint32_t)qi[4] & 0xFF)        | (((uint32_t)qi[5] & 0xFF) << 8)
                | (((uint32_t)qi[6] & 0xFF) << 16) | (((uint32_t)qi[7] & 0xFF) << 24);
    size_t base = (size_t)row * D_DIM + w * 256 + lane * 8;
    *(uint2*)&qx[base] = make_uint2(p0, p1);

    uint32_t f0 =  (uint32_t)to_e4m3((float)qi[0])
                | ((uint32_t)to_e4m3((float)qi[1]) << 8)
                | ((uint32_t)to_e4m3((float)qi[2]) << 16)
                | ((uint32_t)to_e4m3((float)qi[3]) << 24);
    uint32_t f1 =  (uint32_t)to_e4m3((float)qi[4])
                | ((uint32_t)to_e4m3((float)qi[5]) << 8)
                | ((uint32_t)to_e4m3((float)qi[6]) << 16)
                | ((uint32_t)to_e4m3((float)qi[7]) << 24);
    *(uint2*)&qx8[base] = make_uint2(f0, f1);
}

// ============================================================================
// Kernel 2: int8 GEMM (cols [0, NSPLIT)) — the proven R4 kernel.
// Tile 128x128, 256 threads (8 warps, 2Mx4N, warp 64x32), 4-stage cp.async,
// 2 CTAs/SM, fused dequant epilogue.
// ============================================================================
__global__ __launch_bounds__(THREADS, 2) void gemm_s8_kernel(
    const signed char* __restrict__ gA,
    const signed char* __restrict__ gB,
    const float* __restrict__ sx,
    const float* __restrict__ ws,
    const float* __restrict__ bias,
    float* __restrict__ out)
{
    extern __shared__ char smem[];
    uint32_t sbase = smem_u32(smem);
    const uint32_t sA0 = sbase;
    const uint32_t sB0 = sbase + NSTAGE * A_STAGE;

    int tid  = threadIdx.x;
    int lane = tid & 31;
    int wid  = tid >> 5;
    int m0 = blockIdx.x * BM;
    int n0 = blockIdx.y * BN;
    int wm = wid & 1;
    int wn = wid >> 1;
    int Amb = wm * 64;
    int Bnb = wn * 32;
    int i8 = lane & 7, g = lane >> 3;

    int acc[4][4][4];
#pragma unroll
    for (int a = 0; a < 4; a++)
#pragma unroll
        for (int b = 0; b < 4; b++)
#pragma unroll
            for (int c = 0; c < 4; c++) acc[a][b][c] = 0;

    int row0 = tid >> 2, ch0 = tid & 3;
    int row1 = (tid + 256) >> 2;
    const signed char* gA0 = gA + (size_t)(m0 + row0) * D_DIM + ch0 * 16;
    const signed char* gA1 = gA + (size_t)(m0 + row1) * D_DIM + ch0 * 16;
    const signed char* gB0 = gB + (size_t)(n0 + row0) * D_DIM + ch0 * 16;
    const signed char* gB1 = gB + (size_t)(n0 + row1) * D_DIM + ch0 * 16;
    uint32_t off0 = tile_off(row0, ch0);
    uint32_t off1 = tile_off(row1, ch0);

    auto load_stage = [&](int kt, int buf) {
        int kb = kt * BK;
        uint32_t dA = sA0 + buf * A_STAGE;
        uint32_t dB = sB0 + buf * B_STAGE;
        CP_ASYNC16(dA + off0, gA0 + kb);
        CP_ASYNC16(dA + off1, gA1 + kb);
        CP_ASYNC16(dB + off0, gB0 + kb);
        CP_ASYNC16(dB + off1, gB1 + kb);
    };

    uint32_t aoffs[4][2], boffs[2][2];
#pragma unroll
    for (int mb = 0; mb < 4; mb++) {
        int row = Amb + mb * 16 + i8 + (g & 1) * 8;
#pragma unroll
        for (int ks = 0; ks < 2; ks++)
            aoffs[mb][ks] = tile_off(row, ks * 2 + (g >> 1));
    }
#pragma unroll
    for (int np = 0; np < 2; np++) {
        int row = Bnb + np * 16 + i8 + (g >> 1) * 8;
#pragma unroll
        for (int ks = 0; ks < 2; ks++)
            boffs[np][ks] = tile_off(row, ks * 2 + (g & 1));
    }

#pragma unroll
    for (int s = 0; s < NSTAGE - 1; s++) {
        load_stage(s, s);
        CP_COMMIT();
    }

    for (int kt = 0; kt < KT_ITERS; kt++) {
        CP_WAIT2();
        __syncthreads();

        int ldkt = kt + NSTAGE - 1;
        if (ldkt < KT_ITERS) load_stage(ldkt, ldkt & (NSTAGE - 1));
        CP_COMMIT();

        uint32_t sA = sA0 + (kt & (NSTAGE - 1)) * A_STAGE;
        uint32_t sB = sB0 + (kt & (NSTAGE - 1)) * B_STAGE;

#pragma unroll
        for (int ks = 0; ks < 2; ks++) {
            uint32_t a[4][4], b[2][4];
#pragma unroll
            for (int mb = 0; mb < 4; mb++) LDM_X4(a[mb], sA + aoffs[mb][ks]);
#pragma unroll
            for (int np = 0; np < 2; np++) LDM_X4(b[np], sB + boffs[np][ks]);
#pragma unroll
            for (int mb = 0; mb < 4; mb++)
#pragma unroll
                for (int nb = 0; nb < 4; nb++)
                    MMA_S8(acc[mb][nb], a[mb],
                           b[nb >> 1][(nb & 1) * 2], b[nb >> 1][(nb & 1) * 2 + 1]);
        }
    }

#pragma unroll
    for (int mb = 0; mb < 4; mb++) {
        int r0 = m0 + Amb + mb * 16 + (lane >> 2);
        float sx0 = sx[r0], sx1 = sx[r0 + 8];
#pragma unroll
        for (int nb = 0; nb < 4; nb++) {
            int c0 = n0 + Bnb + nb * 8 + (lane & 3) * 2;
            float w0 = ws[c0],  w1 = ws[c0 + 1];
            float f0 = bias[c0], f1 = bias[c0 + 1];
            float2 v0, v1;
            v0.x = (float)acc[mb][nb][0] * sx0 * w0 + f0;
            v0.y = (float)acc[mb][nb][1] * sx0 * w1 + f1;
            v1.x = (float)acc[mb][nb][2] * sx1 * w0 + f0;
            v1.y = (float)acc[mb][nb][3] * sx1 * w1 + f1;
            *(float2*)&out[(size_t)r0 * D_DIM + c0]       = v0;
            *(float2*)&out[(size_t)(r0 + 8) * D_DIM + c0] = v1;
        }
    }
}

// ============================================================================
// Kernel 3: e4m3 GEMM (cols [NSPLIT, 4096)) — identical structure, f32 acc.
// Exact: operands are small integers, products <= 56, sums < 2^24.
// ============================================================================
__global__ __launch_bounds__(THREADS, 2) void gemm_f8_kernel(
    const unsigned char* __restrict__ gA,
    const unsigned char* __restrict__ gB,
    const float* __restrict__ sx,
    const float* __restrict__ ws,
    const float* __restrict__ bias,
    float* __restrict__ out)
{
    extern __shared__ char smem[];
    uint32_t sbase = smem_u32(smem);
    const uint32_t sA0 = sbase;
    const uint32_t sB0 = sbase + NSTAGE * A_STAGE;

    int tid  = threadIdx.x;
    int lane = tid & 31;
    int wid  = tid >> 5;
    int m0 = blockIdx.x * BM;
    int n0 = NSPLIT + blockIdx.y * BN;
    int wm = wid & 1;
    int wn = wid >> 1;
    int Amb = wm * 64;
    int Bnb = wn * 32;
    int i8 = lane & 7, g = lane >> 3;

    float acc[4][4][4];
#pragma unroll
    for (int a = 0; a < 4; a++)
#pragma unroll
        for (int b = 0; b < 4; b++)
#pragma unroll
            for (int c = 0; c < 4; c++) acc[a][b][c] = 0.0f;

    int row0 = tid >> 2, ch0 = tid & 3;
    int row1 = (tid + 256) >> 2;
    const unsigned char* gA0 = gA + (size_t)(m0 + row0) * D_DIM + ch0 * 16;
    const unsigned char* gA1 = gA + (size_t)(m0 + row1) * D_DIM + ch0 * 16;
    const unsigned char* gB0 = gB + (size_t)(n0 + row0) * D_DIM + ch0 * 16;
    const unsigned char* gB1 = gB + (size_t)(n0 + row1) * D_DIM + ch0 * 16;
    uint32_t off0 = tile_off(row0, ch0);
    uint32_t off1 = tile_off(row1, ch0);

    auto load_stage = [&](int kt, int buf) {
        int kb = kt * BK;
        uint32_t dA = sA0 + buf * A_STAGE;
        uint32_t dB = sB0 + buf * B_STAGE;
        CP_ASYNC16(dA + off0, gA0 + kb);
        CP_ASYNC16(dA + off1, gA1 + kb);
        CP_ASYNC16(dB + off0, gB0 + kb);
        CP_ASYNC16(dB + off1, gB1 + kb);
    };

    uint32_t aoffs[4][2], boffs[2][2];
#pragma unroll
    for (int mb = 0; mb < 4; mb++) {
        int row = Amb + mb * 16 + i8 + (g & 1) * 8;
#pragma unroll
        for (int ks = 0; ks < 2; ks++)
            aoffs[mb][ks] = tile_off(row, ks * 2 + (g >> 1));
    }
#pragma unroll
    for (int np = 0; np < 2; np++) {
        int row = Bnb + np * 16 + i8 + (g >> 1) * 8;
#pragma unroll
        for (int ks = 0; ks < 2; ks++)
            boffs[np][ks] = tile_off(row, ks * 2 + (g & 1));
    }

#pragma unroll
    for (int s = 0; s < NSTAGE - 1; s++) {
        load_stage(s, s);
        CP_COMMIT();
    }

    for (int kt = 0; kt < KT_ITERS; kt++) {
        CP_WAIT2();
        __syncthreads();

        int ldkt = kt + NSTAGE - 1;
        if (ldkt < KT_ITERS) load_stage(ldkt, ldkt & (NSTAGE - 1));
        CP_COMMIT();

        uint32_t sA = sA0 + (kt & (NSTAGE - 1)) * A_STAGE;
        uint32_t sB = sB0 + (kt & (NSTAGE - 1)) * B_STAGE;

#pragma unroll
        for (int ks = 0; ks < 2; ks++) {
            uint32_t a[4][4], b[2][4];
#pragma unroll
            for (int mb = 0; mb < 4; mb++) LDM_X4(a[mb], sA + aoffs[mb][ks]);
#pragma unroll
            for (int np = 0; np < 2; np++) LDM_X4(b[np], sB + boffs[np][ks]);
#pragma unroll
            for (int mb = 0; mb < 4; mb++)
#pragma unroll
                for (int nb = 0; nb < 4; nb++)
                    MMA_E4M3(acc[mb][nb], a[mb],
                             b[nb >> 1][(nb & 1) * 2], b[nb >> 1][(nb & 1) * 2 + 1]);
        }
    }

#pragma unroll
    for (int mb = 0; mb < 4; mb++) {
        int r0 = m0 + Amb + mb * 16 + (lane >> 2);
        float sx0 = sx[r0], sx1 = sx[r0 + 8];
#pragma unroll
        for (int nb = 0; nb < 4; nb++) {
            int c0 = n0 + Bnb + nb * 8 + (lane & 3) * 2;
            float w0 = ws[c0],  w1 = ws[c0 + 1];
            float f0 = bias[c0], f1 = bias[c0 + 1];
            float2 v0, v1;
            v0.x = acc[mb][nb][0] * sx0 * w0 + f0;
            v0.y = acc[mb][nb][1] * sx0 * w1 + f1;
            v1.x = acc[mb][nb][2] * sx1 * w0 + f0;
            v1.y = acc[mb][nb][3] * sx1 * w1 + f1;
            *(float2*)&out[(size_t)r0 * D_DIM + c0]       = v0;
            *(float2*)&out[(size_t)(r0 + 8) * D_DIM + c0] = v1;
        }
    }
}

// ============================================================================
// Host launcher
// ============================================================================
extern "C" void kernel_launch(void* const* d_in, const int* in_sizes, int n_in,
                              void* d_out, int out_size)
{
    const float* x    = (const float*)d_in[0];
    const int*   wi   = (const int*)  d_in[1];
    const float* wsc  = (const float*)d_in[2];
    const float* bias = (const float*)d_in[3];
    float*       out  = (float*)d_out;

    void *pqx = nullptr, *pwq = nullptr, *pqx8 = nullptr, *pwq8 = nullptr, *psx = nullptr;
    cudaGetSymbolAddress(&pqx,  g_qx);
    cudaGetSymbolAddress(&pwq,  g_wq);
    cudaGetSymbolAddress(&pqx8, g_qx8);
    cudaGetSymbolAddress(&pwq8, g_wq8);
    cudaGetSymbolAddress(&psx,  g_sx);

    static bool attr_set = false;
    if (!attr_set) {
        cudaFuncSetAttribute(gemm_s8_kernel, cudaFuncAttributeMaxDynamicSharedMemorySize,
                             NSTAGE * STAGE_BYTES);
        cudaFuncSetAttribute(gemm_f8_kernel, cudaFuncAttributeMaxDynamicSharedMemorySize,
                             NSTAGE * STAGE_BYTES);
        attr_set = true;
    }

    // 1) fused prep (dual-format)
    prep_kernel<<<8192, 512>>>(x, (const int4*)wi,
                               (signed char*)pqx, (signed char*)pwq,
                               (unsigned char*)pqx8, (unsigned char*)pwq8,
                               (float*)psx);

    // 2) s8 GEMM on cols [0, NSPLIT)
    dim3 grid_s8(D_DIM / BM, NSPLIT / BN, 1);
    gemm_s8_kernel<<<grid_s8, THREADS, NSTAGE * STAGE_BYTES>>>(
        (const signed char*)pqx, (const signed char*)pwq,
        (const float*)psx, wsc, bias, out);

    // 3) e4m3 GEMM on cols [NSPLIT, 4096)
    dim3 grid_f8(D_DIM / BM, (D_DIM - NSPLIT) / BN, 1);
    gemm_f8_kernel<<<grid_f8, THREADS, NSTAGE * STAGE_BYTES>>>(
        (const unsigned char*)pqx8, (const unsigned char*)pwq8,
        (const float*)psx, wsc, bias, out);
}